// round 12
// baseline (speedup 1.0000x reference)
#include <cuda_runtime.h>
#include <cuda_bf16.h>
#include <cuda_fp16.h>
#include <cstdint>
#include <cstddef>

#define SEQ 2048
#define EMB 768
#define NH  12
#define HD  64
#define MU_F (1.0f/2048.0f)
#define PADK 40     // bf16 GEMM smem row stride (elements)
#define APAD 48     // fp8 av smem row stride (bytes)
#define VSCALE 16.0f

// sink tiling: 32-row blocks, 4 tiles of 8 rows, 2-stage cp.async
#define TROWS 8
#define TPAD  2064
#define TILEB (TROWS * TPAD)            // 16512

// ---------------- scratch (device globals; no allocation allowed) -------------
__device__ __nv_bfloat16 g_Xb[SEQ*EMB];
__device__ __nv_bfloat16 g_Wt[4*EMB*EMB];           // Wq,Wk,Wv,Wo transposed [n][k]
__device__ __nv_bfloat16 g_QKV[3*SEQ*EMB];          // Q(=q/8), K, V  bf16
__device__ unsigned char g_E8[(size_t)NH*SEQ*SEQ];  // exp(QK^T/8) e4m3 (50.3MB)
__device__ unsigned char g_Vt8[NH*HD*SEQ];          // (diag(b) V)^T * 16, e4m3
__device__ __nv_bfloat16 g_ctxb[SEQ*EMB];
__device__ float g_r[6*NH*SEQ];                     // raw Sinkhorn sums r0..r5
__device__ float g_y[SEQ*EMB];

// ============================ PTX helpers =====================================
__device__ __forceinline__ uint32_t smem_u32(const void* p) {
    uint32_t a;
    asm("{ .reg .u64 t; cvta.to.shared.u64 t, %1; cvt.u32.u64 %0, t; }"
        : "=r"(a) : "l"(p));
    return a;
}
__device__ __forceinline__ void cpa16(uint32_t dst, const void* src) {
    asm volatile("cp.async.cg.shared.global [%0], [%1], 16;" :: "r"(dst), "l"(src));
}
#define CP_COMMIT() asm volatile("cp.async.commit_group;" ::: "memory")
#define CP_WAIT1()  asm volatile("cp.async.wait_group 1;" ::: "memory")
#define CP_WAIT0()  asm volatile("cp.async.wait_group 0;" ::: "memory")

__device__ __forceinline__ void ldsm4(uint32_t& r0, uint32_t& r1, uint32_t& r2,
                                      uint32_t& r3, uint32_t addr) {
    asm volatile("ldmatrix.sync.aligned.m8n8.x4.shared.b16 {%0,%1,%2,%3}, [%4];"
        : "=r"(r0), "=r"(r1), "=r"(r2), "=r"(r3) : "r"(addr));
}
__device__ __forceinline__ void mma16816(float* c, const uint32_t* a, const uint32_t* b) {
    asm volatile("mma.sync.aligned.m16n8k16.row.col.f32.bf16.bf16.f32 "
        "{%0,%1,%2,%3}, {%4,%5,%6,%7}, {%8,%9}, {%0,%1,%2,%3};"
        : "+f"(c[0]), "+f"(c[1]), "+f"(c[2]), "+f"(c[3])
        : "r"(a[0]), "r"(a[1]), "r"(a[2]), "r"(a[3]), "r"(b[0]), "r"(b[1]));
}
__device__ __forceinline__ void mma16832q(float* c, const uint32_t* a, const uint32_t* b) {
    asm volatile("mma.sync.aligned.m16n8k32.row.col.f32.e4m3.e4m3.f32 "
        "{%0,%1,%2,%3}, {%4,%5,%6,%7}, {%8,%9}, {%0,%1,%2,%3};"
        : "+f"(c[0]), "+f"(c[1]), "+f"(c[2]), "+f"(c[3])
        : "r"(a[0]), "r"(a[1]), "r"(a[2]), "r"(a[3]), "r"(b[0]), "r"(b[1]));
}

// fp8 e4m3 pack/unpack
__device__ __forceinline__ uint16_t pk_e4m3(float lo, float hi) {
    uint16_t r;
    asm("cvt.rn.satfinite.e4m3x2.f32 %0, %1, %2;" : "=h"(r) : "f"(hi), "f"(lo));
    return r;
}
__device__ __forceinline__ void dec4(uint32_t w, float2& lo, float2& hi) {
    uint32_t f0, f1;
    asm("cvt.rn.f16x2.e4m3x2 %0, %1;" : "=r"(f0) : "h"((uint16_t)(w & 0xffffu)));
    asm("cvt.rn.f16x2.e4m3x2 %0, %1;" : "=r"(f1) : "h"((uint16_t)(w >> 16)));
    lo = __half22float2(*(__half2*)&f0);
    hi = __half22float2(*(__half2*)&f1);
}

// ---------------- mma.sync block-GEMM core, 3-stage pipeline (bf16) ------------
template<int BN>
__device__ __forceinline__ void gemm_core3(
    const __nv_bfloat16* __restrict__ A, int lda,
    const __nv_bfloat16* __restrict__ B, int ldb,
    int nchunks, __nv_bfloat16* As, __nv_bfloat16* Bs,
    float acc[2][BN/16][4])
{
    constexpr int NF = BN / 16;
    const int tid = threadIdx.x;
    const int lane = tid & 31, wid = tid >> 5;
    const int wm = wid >> 1, wn = wid & 1;
    const uint32_t asb = smem_u32(As), bsb = smem_u32(Bs);
    const uint32_t ASTG = 128 * PADK * 2, BSTG = BN * PADK * 2;

    const int lr = tid >> 2, lc = (tid & 3) * 8;
    const uint32_t adst = (uint32_t)(lr * PADK + lc) * 2;
    const uint32_t bdst = adst;

    uint32_t aoff[2], boff[NF / 2];
#pragma unroll
    for (int mi = 0; mi < 2; mi++) {
        int r = wm * 32 + mi * 16 + (lane & 15);
        int c = (lane >> 4) * 8;
        aoff[mi] = (uint32_t)(r * PADK + c) * 2;
    }
#pragma unroll
    for (int n2 = 0; n2 < NF / 2; n2++) {
        int g = lane >> 3;
        int r = wn * (BN / 2) + n2 * 16 + ((g >> 1) << 3) + (lane & 7);
        int c = (g & 1) * 8;
        boff[n2] = (uint32_t)(r * PADK + c) * 2;
    }

#pragma unroll
    for (int mi = 0; mi < 2; mi++)
#pragma unroll
        for (int ni = 0; ni < NF; ni++)
#pragma unroll
            for (int q = 0; q < 4; q++) acc[mi][ni][q] = 0.f;

    auto issue = [&](int c, int stg) {
        const __nv_bfloat16* Ac = A + c * 32;
        const __nv_bfloat16* Bc = B + c * 32;
        uint32_t ad = asb + (uint32_t)stg * ASTG, bd = bsb + (uint32_t)stg * BSTG;
        cpa16(ad + adst, Ac + (size_t)lr * lda + lc);
        cpa16(ad + adst + 64u * PADK * 2, Ac + (size_t)(lr + 64) * lda + lc);
        cpa16(bd + bdst, Bc + (size_t)lr * ldb + lc);
        if (BN == 128)
            cpa16(bd + bdst + 64u * PADK * 2, Bc + (size_t)(lr + 64) * ldb + lc);
        CP_COMMIT();
    };

    issue(0, 0);
    if (nchunks > 1) issue(1, 1);

    int s = 0, w = 2;
    for (int c = 0; c < nchunks; c++) {
        if (c + 1 < nchunks) { CP_WAIT1(); } else { CP_WAIT0(); }
        __syncthreads();
        if (c + 2 < nchunks) issue(c + 2, w);

        uint32_t ab = asb + (uint32_t)s * ASTG, bb = bsb + (uint32_t)s * BSTG;
#pragma unroll
        for (int ks = 0; ks < 2; ks++) {
            uint32_t af[2][4];
            ldsm4(af[0][0], af[0][1], af[0][2], af[0][3], ab + aoff[0] + ks * 32);
            ldsm4(af[1][0], af[1][1], af[1][2], af[1][3], ab + aoff[1] + ks * 32);
#pragma unroll
            for (int n2 = 0; n2 < NF / 2; n2++) {
                uint32_t bf[4];
                ldsm4(bf[0], bf[1], bf[2], bf[3], bb + boff[n2] + ks * 32);
                mma16816(acc[0][2 * n2],     af[0], bf + 0);
                mma16816(acc[0][2 * n2 + 1], af[0], bf + 2);
                mma16816(acc[1][2 * n2],     af[1], bf + 0);
                mma16816(acc[1][2 * n2 + 1], af[1], bf + 2);
            }
        }
        s = (s == 2) ? 0 : s + 1;
        w = (w == 2) ? 0 : w + 1;
    }
}

#define SMEM_GEMM (6 * 128 * PADK * 2)                      // 61440
#define SMEM_AV   (3 * 128 * APAD + 3 * 64 * APAD)          // 27648

// ---------------- fused prep: zero r, cvt X->bf16, transpose W -----------------
__global__ __launch_bounds__(256) void prep_kernel(
    const float* __restrict__ X,
    const float* __restrict__ Wq, const float* __restrict__ Wk,
    const float* __restrict__ Wv, const float* __restrict__ Wo,
    __nv_bfloat16* __restrict__ Xb, __nv_bfloat16* __restrict__ Wt,
    float* __restrict__ r)
{
    __shared__ float t[32][33];
    int b = blockIdx.x;
    if (b < 576) {                       // zero 6*NH*SEQ floats
        r[b * 256 + threadIdx.x] = 0.f;
        return;
    }
    b -= 576;
    if (b < 1536) {                      // cvt X
        int i = (b * 256 + threadIdx.x) * 4;
        float4 v = *(const float4*)(X + i);
        __nv_bfloat162 p0 = __floats2bfloat162_rn(v.x, v.y);
        __nv_bfloat162 p1 = __floats2bfloat162_rn(v.z, v.w);
        uint2 o = make_uint2(*(uint32_t*)&p0, *(uint32_t*)&p1);
        *(uint2*)(Xb + i) = o;
        return;
    }
    b -= 1536;                           // wtrans: 4 * 24 * 24 blocks
    int z = b / 576;
    int rem = b % 576;
    int n0 = (rem % 24) * 32, k0 = (rem / 24) * 32;
    const float* W = (z == 0) ? Wq : (z == 1) ? Wk : (z == 2) ? Wv : Wo;
    int tx = threadIdx.x & 31, ty = threadIdx.x >> 5;
#pragma unroll
    for (int q = 0; q < 4; q++)
        t[ty + q * 8][tx] = W[(size_t)(k0 + ty + q * 8) * EMB + n0 + tx];
    __syncthreads();
    __nv_bfloat16* O = Wt + (size_t)z * EMB * EMB;
#pragma unroll
    for (int q = 0; q < 4; q++)
        O[(size_t)(n0 + ty + q * 8) * EMB + k0 + tx] = __float2bfloat16(t[tx][ty + q * 8]);
}

// Vt8[h][d][j] = e4m3( V[j][h*64+d] * (MU / r5_raw[h][j]) * 16 )
__global__ __launch_bounds__(256) void vt_prep_kernel(
    const __nv_bfloat16* __restrict__ Vb, const float* __restrict__ braw,
    unsigned char* __restrict__ Vt)
{
    int h = blockIdx.y, j0 = blockIdx.x * 64;
    __shared__ float t[64][65];
    int tid = threadIdx.x;
    int jj = tid >> 2, d0 = (tid & 3) * 16;
    const __nv_bfloat16* src = Vb + (size_t)(j0 + jj) * EMB + h * HD + d0;
    __nv_bfloat16 tmp[16];
    *(uint4*)tmp = *(const uint4*)src;
    *(uint4*)(tmp + 8) = *(const uint4*)(src + 8);
#pragma unroll
    for (int q = 0; q < 16; q++) t[jj][d0 + q] = __bfloat162float(tmp[q]);
    __syncthreads();
    int dd = tid >> 2, jb = (tid & 3) * 16;
    uint16_t o[8];
#pragma unroll
    for (int q = 0; q < 8; q++) {
        int j = j0 + jb + 2 * q;
        float b0 = VSCALE * MU_F / braw[h * SEQ + j];
        float b1 = VSCALE * MU_F / braw[h * SEQ + j + 1];
        o[q] = pk_e4m3(t[jb + 2 * q][dd] * b0, t[jb + 2 * q + 1][dd] * b1);
    }
    unsigned char* dst = Vt + ((size_t)h * HD + dd) * SEQ + j0 + jb;
    *(uint4*)dst = *(uint4*)o;
}

// ---------------- QKV projection ----------------------------------------------
__global__ __launch_bounds__(256, 2) void proj_kernel(
    const __nv_bfloat16* __restrict__ Xb, const __nv_bfloat16* __restrict__ Wt,
    const float* __restrict__ bq, const float* __restrict__ bk,
    const float* __restrict__ bv, __nv_bfloat16* __restrict__ Out)
{
    extern __shared__ char dsm[];
    __nv_bfloat16* As = (__nv_bfloat16*)dsm;
    __nv_bfloat16* Bs = (__nv_bfloat16*)(dsm + 3 * 128 * PADK * 2);
    int z = blockIdx.z;
    int n0 = blockIdx.x * 128, i0 = blockIdx.y * 128;
    const float* bias = (z == 0) ? bq : (z == 1) ? bk : bv;
    float scale = (z == 0) ? 0.125f : 1.0f;

    float acc[2][8][4];
    gemm_core3<128>(Xb + (size_t)i0 * EMB, EMB,
                    Wt + (size_t)z * EMB * EMB + (size_t)n0 * EMB, EMB,
                    EMB / 32, As, Bs, acc);

    int lane = threadIdx.x & 31, wid = threadIdx.x >> 5;
    int wm = wid >> 1, wn = wid & 1;
    int r0 = wm * 32 + (lane >> 2), cb = wn * 64 + (lane & 3) * 2;
    __nv_bfloat16* O = Out + (size_t)z * SEQ * EMB;
#pragma unroll
    for (int mi = 0; mi < 2; mi++)
#pragma unroll
        for (int m8 = 0; m8 < 2; m8++) {
            int row = i0 + r0 + mi * 16 + m8 * 8;
#pragma unroll
            for (int ni = 0; ni < 8; ni++) {
                int col = n0 + cb + ni * 8;
                float f0 = (acc[mi][ni][m8 * 2 + 0] + bias[col])     * scale;
                float f1 = (acc[mi][ni][m8 * 2 + 1] + bias[col + 1]) * scale;
                __nv_bfloat162 p = __floats2bfloat162_rn(f0, f1);
                *(uint32_t*)(O + (size_t)row * EMB + col) = *(uint32_t*)&p;
            }
        }
}

// ---------------- E = exp(QK^T/8) (e4m3) + raw row sums -> r0 ------------------
__global__ __launch_bounds__(256, 2) void qk_kernel(
    const __nv_bfloat16* __restrict__ QKV, float* __restrict__ rsumg)
{
    extern __shared__ char dsm[];
    __nv_bfloat16* As = (__nv_bfloat16*)dsm;
    __nv_bfloat16* Bs = (__nv_bfloat16*)(dsm + 3 * 128 * PADK * 2);
    int j0 = blockIdx.x * 128, i0 = blockIdx.y * 128, h = blockIdx.z;

    float acc[2][8][4];
    gemm_core3<128>(QKV + (size_t)i0 * EMB + h * HD, EMB,
                    QKV + (size_t)SEQ * EMB + (size_t)j0 * EMB + h * HD, EMB,
                    HD / 32, As, Bs, acc);

    unsigned char* Et = (unsigned char*)dsm;
    float* rsumS = (float*)(dsm + 128 * 144);
    int tid = threadIdx.x, lane = tid & 31, wid = tid >> 5;
    int wm = wid >> 1, wn = wid & 1;
    int r0 = wm * 32 + (lane >> 2), cb = wn * 64 + (lane & 3) * 2;

    __syncthreads();
    if (tid < 128) rsumS[tid] = 0.f;

    float rs_sv[4];
    int lrow_sv[4];
    int idx = 0;
#pragma unroll
    for (int mi = 0; mi < 2; mi++)
#pragma unroll
        for (int m8 = 0; m8 < 2; m8++) {
            int lrow = r0 + mi * 16 + m8 * 8;
            float rs = 0.f;
#pragma unroll
            for (int ni = 0; ni < 8; ni++) {
                float e0 = __expf(acc[mi][ni][m8 * 2 + 0]);
                float e1 = __expf(acc[mi][ni][m8 * 2 + 1]);
                rs += e0 + e1;
                *(uint16_t*)(Et + lrow * 144 + cb + ni * 8) = pk_e4m3(e0, e1);
            }
            rs += __shfl_xor_sync(0xffffffffu, rs, 1);
            rs += __shfl_xor_sync(0xffffffffu, rs, 2);
            rs_sv[idx] = rs; lrow_sv[idx] = lrow; idx++;
        }
    __syncthreads();
#pragma unroll
    for (int q = 0; q < 4; q++)
        if ((lane & 3) == 0) atomicAdd(&rsumS[lrow_sv[q]], rs_sv[q]);
    __syncthreads();

    int row = tid >> 1, half = (tid & 1) * 64;
    const uint4* src = (const uint4*)(Et + row * 144 + half);
    uint4* dst = (uint4*)(g_E8 + ((size_t)h * SEQ + i0 + row) * SEQ + j0 + half);
    dst[0] = src[0]; dst[1] = src[1]; dst[2] = src[2]; dst[3] = src[3];
    if (tid < 128)
        atomicAdd(&rsumg[h * SEQ + i0 + tid], rsumS[tid]);
}

// ---------------- Sinkhorn streaming pass (cp.async staged, 41KB smem) ---------
// Block: 32 rows. 4 tiles of 8 rows, 2-stage cp.async double buffer.
// DO_ROW=true : rowout[i] = s_i = sum_j E_ij*(MU/inraw[j]); colout[j] += E_ij*(MU/s_i)
// DO_ROW=false: colout[j] += E_ij*(MU/inraw[i])
template<bool DO_ROW>
__global__ __launch_bounds__(256, 4) void sink_pass(
    const float* __restrict__ inraw, float* __restrict__ rowout,
    float* __restrict__ colout)
{
    __shared__ float bs[2048];
    __shared__ char tiles[2][TILEB];
    __shared__ float srow[TROWS];
    int h = blockIdx.y, i0 = blockIdx.x * 32;
    int tid = threadIdx.x, lane = tid & 31, wid = tid >> 5;

    if (DO_ROW) {
        for (int j = tid; j < SEQ; j += 256) bs[j] = MU_F / inraw[h * SEQ + j];
    }

    // loader: 8 rows x 2048B; thread t: row=t>>5, 4 segs of 16B at (t&31)*16 + k*512
    const int lrow = tid >> 5, lcb = (tid & 31) * 16;
    const unsigned char* Eb = g_E8 + ((size_t)h * SEQ + i0) * SEQ;
    const uint32_t tbase = smem_u32(tiles);

    auto issue = [&](int t, int stg) {
        const unsigned char* src = Eb + (size_t)(t * TROWS + lrow) * SEQ + lcb;
        uint32_t dst = tbase + (uint32_t)stg * TILEB + lrow * TPAD + lcb;
#pragma unroll
        for (int k = 0; k < 4; k++) cpa16(dst + k * 512, src + k * 512);
        CP_COMMIT();
    };

    float ac[8];
#pragma unroll
    for (int q = 0; q < 8; q++) ac[q] = 0.f;

    issue(0, 0);
    if (DO_ROW) __syncthreads();         // bs ready before row phase

    for (int t = 0; t < 4; t++) {
        int s = t & 1;
        if (t + 1 < 4) { issue(t + 1, s ^ 1); CP_WAIT1(); }
        else { CP_WAIT0(); }
        __syncthreads();

        if (DO_ROW) {
            // warp w computes row w's dot with bs
            const char* trow = tiles[s] + wid * TPAD;
            float sum = 0.f;
#pragma unroll
            for (int k = 0; k < 4; k++) {
                int colb = lane * 16 + k * 512;
                uint4 u = *(const uint4*)(trow + colb);
                const uint32_t wv[4] = {u.x, u.y, u.z, u.w};
#pragma unroll
                for (int m = 0; m < 4; m++) {
                    float2 lo, hi;
                    dec4(wv[m], lo, hi);
                    const float* bp = bs + colb + m * 4;
                    sum += lo.x * bp[0] + lo.y * bp[1] + hi.x * bp[2] + hi.y * bp[3];
                }
            }
#pragma unroll
            for (int o = 16; o; o >>= 1) sum += __shfl_xor_sync(0xffffffffu, sum, o);
            if (lane == 0) {
                rowout[h * SEQ + i0 + t * TROWS + wid] = sum;
                srow[wid] = MU_F / sum;
            }
        } else {
            if (tid < TROWS)
                srow[tid] = MU_F / inraw[h * SEQ + i0 + t * TROWS + tid];
        }
        __syncthreads();

        // column accumulate: thread owns cols tid*8 .. +7
#pragma unroll
        for (int r = 0; r < TROWS; r++) {
            uint2 u = *(const uint2*)(tiles[s] + r * TPAD + tid * 8);
            float a = srow[r];
            float2 lo, hi, lo2, hi2;
            dec4(u.x, lo, hi);
            dec4(u.y, lo2, hi2);
            ac[0] += lo.x * a;  ac[1] += lo.y * a;
            ac[2] += hi.x * a;  ac[3] += hi.y * a;
            ac[4] += lo2.x * a; ac[5] += lo2.y * a;
            ac[6] += hi2.x * a; ac[7] += hi2.y * a;
        }
        __syncthreads();                 // tile s free for reuse
    }

    float* cp = colout + h * SEQ + tid * 8;
#pragma unroll
    for (int q = 0; q < 8; q++) atomicAdd(cp + q, ac[q]);
}

// ---------------- ctx = diag(1/r4) * E * (diag(b) V)  — native fp8 mma ---------
__global__ __launch_bounds__(256, 2) void av_kernel(
    const unsigned char* __restrict__ Vt, const float* __restrict__ araw,
    __nv_bfloat16* __restrict__ ctx)
{
    extern __shared__ char dsm[];
    char* As = dsm;                      // 3 stages 128 x APAD
    char* Bs = dsm + 3 * 128 * APAD;     // 3 stages 64 x APAD
    int i0 = blockIdx.x * 128, h = blockIdx.y;
    const int tid = threadIdx.x, lane = tid & 31, wid = tid >> 5;
    const int wm = wid >> 1, wn = wid & 1;
    const uint32_t asb = smem_u32(As), bsb = smem_u32(Bs);
    const uint32_t ASTG = 128 * APAD, BSTG = 64 * APAD;
    const int NCH = SEQ / 32;

    const int arow = tid >> 1, acol = (tid & 1) * 16;
    const unsigned char* Ag = g_E8 + ((size_t)h * SEQ + i0 + arow) * SEQ + acol;
    const uint32_t adst = (uint32_t)(arow * APAD + acol);
    const int brow = tid >> 1, bcol = (tid & 1) * 16;
    const unsigned char* Bg = Vt + ((size_t)h * HD + brow) * SEQ + bcol;
    const uint32_t bdst = (uint32_t)(brow * APAD + bcol);
    const bool bload = (tid < 128);

    uint32_t aoff[2], boff[2];
#pragma unroll
    for (int mi = 0; mi < 2; mi++) {
        int r = wm * 32 + mi * 16 + (lane & 15);
        aoff[mi] = (uint32_t)(r * APAD + (lane >> 4) * 16);
    }
#pragma unroll
    for (int n2 = 0; n2 < 2; n2++) {
        int g = lane >> 3;
        int r = wn * 32 + n2 * 16 + ((g >> 1) << 3) + (lane & 7);
        boff[n2] = (uint32_t)(r * APAD + (g & 1) * 16);
    }

    float acc[2][4][4];
#pragma unroll
    for (int mi = 0; mi < 2; mi++)
#pragma unroll
        for (int ni = 0; ni < 4; ni++)
#pragma unroll
            for (int q = 0; q < 4; q++) acc[mi][ni][q] = 0.f;

    auto issue = [&](int c, int stg) {
        cpa16(asb + (uint32_t)stg * ASTG + adst, Ag + c * 32);
        if (bload) cpa16(bsb + (uint32_t)stg * BSTG + bdst, Bg + c * 32);
        CP_COMMIT();
    };

    issue(0, 0);
    issue(1, 1);

    int s = 0, w = 2;
    for (int c = 0; c < NCH; c++) {
        if (c + 1 < NCH) { CP_WAIT1(); } else { CP_WAIT0(); }
        __syncthreads();
        if (c + 2 < NCH) issue(c + 2, w);

        uint32_t ab = asb + (uint32_t)s * ASTG, bb = bsb + (uint32_t)s * BSTG;
        uint32_t af[2][4];
        ldsm4(af[0][0], af[0][1], af[0][2], af[0][3], ab + aoff[0]);
        ldsm4(af[1][0], af[1][1], af[1][2], af[1][3], ab + aoff[1]);
#pragma unroll
        for (int n2 = 0; n2 < 2; n2++) {
            uint32_t bf[4];
            ldsm4(bf[0], bf[1], bf[2], bf[3], bb + boff[n2]);
            mma16832q(acc[0][2 * n2],     af[0], bf + 0);
            mma16832q(acc[0][2 * n2 + 1], af[0], bf + 2);
            mma16832q(acc[1][2 * n2],     af[1], bf + 0);
            mma16832q(acc[1][2 * n2 + 1], af[1], bf + 2);
        }
        s = (s == 2) ? 0 : s + 1;
        w = (w == 2) ? 0 : w + 1;
    }

    int r0 = wm * 32 + (lane >> 2), cb = wn * 32 + (lane & 3) * 2;
#pragma unroll
    for (int mi = 0; mi < 2; mi++)
#pragma unroll
        for (int m8 = 0; m8 < 2; m8++) {
            int row = i0 + r0 + mi * 16 + m8 * 8;
            float sc = 1.0f / (araw[h * SEQ + row] * VSCALE);
            __nv_bfloat16* O = ctx + (size_t)row * EMB + h * HD;
#pragma unroll
            for (int ni = 0; ni < 4; ni++) {
                float f0 = acc[mi][ni][m8 * 2 + 0] * sc;
                float f1 = acc[mi][ni][m8 * 2 + 1] * sc;
                __nv_bfloat162 p = __floats2bfloat162_rn(f0, f1);
                *(uint32_t*)(O + cb + ni * 8) = *(uint32_t*)&p;
            }
        }
}

// ---------------- y = ctx @ Wo + bo + X ----------------------------------------
__global__ __launch_bounds__(256, 2) void final_kernel(
    const __nv_bfloat16* __restrict__ ctx, const __nv_bfloat16* __restrict__ Wt,
    const float* __restrict__ bo, const float* __restrict__ X,
    float* __restrict__ Y)
{
    extern __shared__ char dsm[];
    __nv_bfloat16* As = (__nv_bfloat16*)dsm;
    __nv_bfloat16* Bs = (__nv_bfloat16*)(dsm + 3 * 128 * PADK * 2);
    int n0 = blockIdx.x * 128, i0 = blockIdx.y * 128;

    float acc[2][8][4];
    gemm_core3<128>(ctx + (size_t)i0 * EMB, EMB,
                    Wt + (size_t)3 * EMB * EMB + (size_t)n0 * EMB, EMB,
                    EMB / 32, As, Bs, acc);

    int lane = threadIdx.x & 31, wid = threadIdx.x >> 5;
    int wm = wid >> 1, wn = wid & 1;
    int r0 = wm * 32 + (lane >> 2), cb = wn * 64 + (lane & 3) * 2;
#pragma unroll
    for (int mi = 0; mi < 2; mi++)
#pragma unroll
        for (int m8 = 0; m8 < 2; m8++) {
            int row = i0 + r0 + mi * 16 + m8 * 8;
#pragma unroll
            for (int ni = 0; ni < 8; ni++) {
                int col = n0 + cb + ni * 8;
                float2 xv = *(const float2*)(X + (size_t)row * EMB + col);
                float2 o;
                o.x = acc[mi][ni][m8 * 2 + 0] + bo[col]     + xv.x;
                o.y = acc[mi][ni][m8 * 2 + 1] + bo[col + 1] + xv.y;
                *(float2*)(Y + (size_t)row * EMB + col) = o;
            }
        }
}

// ---------------- LayerNorm ---------------------------------------------------
__global__ __launch_bounds__(256) void ln_kernel(
    const float* __restrict__ y, const float* __restrict__ gam,
    const float* __restrict__ bet, float* __restrict__ out)
{
    int row = blockIdx.x;
    const float* yr = y + (size_t)row * EMB;
    int t = threadIdx.x;
    float v0 = yr[t], v1 = yr[t + 256], v2 = yr[t + 512];

    __shared__ float red[8];
    int lane = t & 31, w = t >> 5;

    float s = v0 + v1 + v2;
#pragma unroll
    for (int o = 16; o; o >>= 1) s += __shfl_xor_sync(0xffffffffu, s, o);
    if (lane == 0) red[w] = s;
    __syncthreads();
    float tot = red[0] + red[1] + red[2] + red[3] + red[4] + red[5] + red[6] + red[7];
    float mean = tot * (1.0f / EMB);

    float d0 = v0 - mean, d1 = v1 - mean, d2 = v2 - mean;
    float sq = d0 * d0 + d1 * d1 + d2 * d2;
    __syncthreads();
#pragma unroll
    for (int o = 16; o; o >>= 1) sq += __shfl_xor_sync(0xffffffffu, sq, o);
    if (lane == 0) red[w] = sq;
    __syncthreads();
    float var = (red[0]+red[1]+red[2]+red[3]+red[4]+red[5]+red[6]+red[7]) * (1.0f / EMB);
    float inv = rsqrtf(var + 1e-12f);

    float* outr = out + (size_t)row * EMB;
    outr[t]       = gam[t]       * d0 * inv + bet[t];
    outr[t + 256] = gam[t + 256] * d1 * inv + bet[t + 256];
    outr[t + 512] = gam[t + 512] * d2 * inv + bet[t + 512];
}

// ---------------- launch ------------------------------------------------------
extern "C" void kernel_launch(void* const* d_in, const int* in_sizes, int n_in,
                              void* d_out, int out_size)
{
    const float* X  = (const float*)d_in[0];
    const float* Wq = (const float*)d_in[1];
    const float* bq = (const float*)d_in[2];
    const float* Wk = (const float*)d_in[3];
    const float* bk = (const float*)d_in[4];
    const float* Wv = (const float*)d_in[5];
    const float* bv = (const float*)d_in[6];
    const float* Wo = (const float*)d_in[7];
    const float* bo = (const float*)d_in[8];
    const float* lg = (const float*)d_in[9];
    const float* lb = (const float*)d_in[10];
    float* out = (float*)d_out;

    void *pXb, *pWt, *pQKV, *pVt, *pctx, *pr, *py;
    cudaGetSymbolAddress(&pXb, g_Xb);
    cudaGetSymbolAddress(&pWt, g_Wt);
    cudaGetSymbolAddress(&pQKV, g_QKV);
    cudaGetSymbolAddress(&pVt, g_Vt8);
    cudaGetSymbolAddress(&pctx, g_ctxb);
    cudaGetSymbolAddress(&pr, g_r);
    cudaGetSymbolAddress(&py, g_y);

    __nv_bfloat16* Xb  = (__nv_bfloat16*)pXb;
    __nv_bfloat16* Wt  = (__nv_bfloat16*)pWt;
    __nv_bfloat16* QKV = (__nv_bfloat16*)pQKV;
    unsigned char* Vt  = (unsigned char*)pVt;
    __nv_bfloat16* ctx = (__nv_bfloat16*)pctx;
    float* fr = (float*)pr;
    float* fy = (float*)py;

    float* r0 = fr + 0 * NH * SEQ;
    float* r1 = fr + 1 * NH * SEQ;
    float* r2 = fr + 2 * NH * SEQ;
    float* r3 = fr + 3 * NH * SEQ;
    float* r4 = fr + 4 * NH * SEQ;
    float* r5 = fr + 5 * NH * SEQ;

    cudaFuncSetAttribute(proj_kernel,  cudaFuncAttributeMaxDynamicSharedMemorySize, SMEM_GEMM);
    cudaFuncSetAttribute(qk_kernel,    cudaFuncAttributeMaxDynamicSharedMemorySize, SMEM_GEMM);
    cudaFuncSetAttribute(av_kernel,    cudaFuncAttributeMaxDynamicSharedMemorySize, SMEM_AV);
    cudaFuncSetAttribute(final_kernel, cudaFuncAttributeMaxDynamicSharedMemorySize, SMEM_GEMM);

    prep_kernel<<<576 + 1536 + 2304, 256>>>(X, Wq, Wk, Wv, Wo, Xb, Wt, fr);

    proj_kernel<<<dim3(EMB / 128, SEQ / 128, 3), 256, SMEM_GEMM>>>(Xb, Wt, bq, bk, bv, QKV);

    qk_kernel<<<dim3(SEQ / 128, SEQ / 128, NH), 256, SMEM_GEMM>>>(QKV, r0);

    // Sinkhorn: 3 iterations in 3 E passes (col, fused row+col, fused row+col)
    dim3 gsink(SEQ / 32, NH);            // (64, 12)
    sink_pass<false><<<gsink, 256>>>(r0, nullptr, r1);
    sink_pass<true><<<gsink, 256>>>(r1, r2, r3);
    sink_pass<true><<<gsink, 256>>>(r3, r4, r5);

    vt_prep_kernel<<<dim3(SEQ / 64, NH), 256>>>(QKV + (size_t)2 * SEQ * EMB, r5, Vt);

    av_kernel<<<dim3(SEQ / 128, NH), 256, SMEM_AV>>>(Vt, r4, ctx);

    final_kernel<<<dim3(EMB / 128, SEQ / 128), 256, SMEM_GEMM>>>(ctx, Wt, bo, X, fy);

    ln_kernel<<<SEQ, 256>>>(fy, lg, lb, out);
}

// round 14
// speedup vs baseline: 1.1194x; 1.1194x over previous
#include <cuda_runtime.h>
#include <cuda_bf16.h>
#include <cuda_fp16.h>
#include <cstdint>
#include <cstddef>

#define SEQ 2048
#define EMB 768
#define NH  12
#define HD  64
#define MU_F (1.0f/2048.0f)
#define PADK 40     // bf16 GEMM smem row stride (elements)
#define APAD 48     // fp8 av smem row stride (bytes)
#define VSCALE 16.0f

// sink-pass tiling (round-9 champion config)
#define TROWS 16
#define TPAD  2064
#define TILEB (TROWS * TPAD)            // 33024
#define SINK_ROWS 64
#define SINK_NT (SINK_ROWS / TROWS)     // 4
#define SMEM_SINK0 (2 * TILEB + 64)             // col-only: 66112
#define SMEM_SINK1 (2 * TILEB + 64 + 2048 * 4)  // fused:    74304

// ---------------- scratch (device globals; no allocation allowed) -------------
__device__ __nv_bfloat16 g_Xb[SEQ*EMB];
__device__ __nv_bfloat16 g_Wt[4*EMB*EMB];           // Wq,Wk,Wv,Wo transposed [n][k]
__device__ __nv_bfloat16 g_QKV[3*SEQ*EMB];          // Q(=q/8), K, V  bf16
__device__ unsigned char g_E8[(size_t)NH*SEQ*SEQ];  // exp(QK^T/8) e4m3 (50.3MB)
__device__ unsigned char g_Vt8[NH*HD*SEQ];          // (diag(b) V)^T * 16, e4m3
__device__ __nv_bfloat16 g_ctxb[SEQ*EMB];
__device__ float g_r[6*NH*SEQ];                     // raw Sinkhorn sums r0..r5
__device__ float g_y[SEQ*EMB];

// ============================ PTX helpers =====================================
__device__ __forceinline__ uint32_t smem_u32(const void* p) {
    uint32_t a;
    asm("{ .reg .u64 t; cvta.to.shared.u64 t, %1; cvt.u32.u64 %0, t; }"
        : "=r"(a) : "l"(p));
    return a;
}
__device__ __forceinline__ void cpa16(uint32_t dst, const void* src) {
    asm volatile("cp.async.cg.shared.global [%0], [%1], 16;" :: "r"(dst), "l"(src));
}
#define CP_COMMIT() asm volatile("cp.async.commit_group;" ::: "memory")
#define CP_WAIT1()  asm volatile("cp.async.wait_group 1;" ::: "memory")
#define CP_WAIT0()  asm volatile("cp.async.wait_group 0;" ::: "memory")

__device__ __forceinline__ void ldsm4(uint32_t& r0, uint32_t& r1, uint32_t& r2,
                                      uint32_t& r3, uint32_t addr) {
    asm volatile("ldmatrix.sync.aligned.m8n8.x4.shared.b16 {%0,%1,%2,%3}, [%4];"
        : "=r"(r0), "=r"(r1), "=r"(r2), "=r"(r3) : "r"(addr));
}
__device__ __forceinline__ void mma16816(float* c, const uint32_t* a, const uint32_t* b) {
    asm volatile("mma.sync.aligned.m16n8k16.row.col.f32.bf16.bf16.f32 "
        "{%0,%1,%2,%3}, {%4,%5,%6,%7}, {%8,%9}, {%0,%1,%2,%3};"
        : "+f"(c[0]), "+f"(c[1]), "+f"(c[2]), "+f"(c[3])
        : "r"(a[0]), "r"(a[1]), "r"(a[2]), "r"(a[3]), "r"(b[0]), "r"(b[1]));
}
__device__ __forceinline__ void mma16832q(float* c, const uint32_t* a, const uint32_t* b) {
    asm volatile("mma.sync.aligned.m16n8k32.row.col.f32.e4m3.e4m3.f32 "
        "{%0,%1,%2,%3}, {%4,%5,%6,%7}, {%8,%9}, {%0,%1,%2,%3};"
        : "+f"(c[0]), "+f"(c[1]), "+f"(c[2]), "+f"(c[3])
        : "r"(a[0]), "r"(a[1]), "r"(a[2]), "r"(a[3]), "r"(b[0]), "r"(b[1]));
}

// fp8 e4m3 pack/unpack
__device__ __forceinline__ uint16_t pk_e4m3(float lo, float hi) {
    uint16_t r;
    asm("cvt.rn.satfinite.e4m3x2.f32 %0, %1, %2;" : "=h"(r) : "f"(hi), "f"(lo));
    return r;
}
__device__ __forceinline__ void dec4(uint32_t w, float2& lo, float2& hi) {
    uint32_t f0, f1;
    asm("cvt.rn.f16x2.e4m3x2 %0, %1;" : "=r"(f0) : "h"((uint16_t)(w & 0xffffu)));
    asm("cvt.rn.f16x2.e4m3x2 %0, %1;" : "=r"(f1) : "h"((uint16_t)(w >> 16)));
    lo = __half22float2(*(__half2*)&f0);
    hi = __half22float2(*(__half2*)&f1);
}

// ---------------- mma.sync block-GEMM core, 3-stage pipeline (bf16) ------------
template<int BN>
__device__ __forceinline__ void gemm_core3(
    const __nv_bfloat16* __restrict__ A, int lda,
    const __nv_bfloat16* __restrict__ B, int ldb,
    int nchunks, __nv_bfloat16* As, __nv_bfloat16* Bs,
    float acc[2][BN/16][4])
{
    constexpr int NF = BN / 16;
    const int tid = threadIdx.x;
    const int lane = tid & 31, wid = tid >> 5;
    const int wm = wid >> 1, wn = wid & 1;
    const uint32_t asb = smem_u32(As), bsb = smem_u32(Bs);
    const uint32_t ASTG = 128 * PADK * 2, BSTG = BN * PADK * 2;

    const int lr = tid >> 2, lc = (tid & 3) * 8;
    const uint32_t adst = (uint32_t)(lr * PADK + lc) * 2;
    const uint32_t bdst = adst;

    uint32_t aoff[2], boff[NF / 2];
#pragma unroll
    for (int mi = 0; mi < 2; mi++) {
        int r = wm * 32 + mi * 16 + (lane & 15);
        int c = (lane >> 4) * 8;
        aoff[mi] = (uint32_t)(r * PADK + c) * 2;
    }
#pragma unroll
    for (int n2 = 0; n2 < NF / 2; n2++) {
        int g = lane >> 3;
        int r = wn * (BN / 2) + n2 * 16 + ((g >> 1) << 3) + (lane & 7);
        int c = (g & 1) * 8;
        boff[n2] = (uint32_t)(r * PADK + c) * 2;
    }

#pragma unroll
    for (int mi = 0; mi < 2; mi++)
#pragma unroll
        for (int ni = 0; ni < NF; ni++)
#pragma unroll
            for (int q = 0; q < 4; q++) acc[mi][ni][q] = 0.f;

    auto issue = [&](int c, int stg) {
        const __nv_bfloat16* Ac = A + c * 32;
        const __nv_bfloat16* Bc = B + c * 32;
        uint32_t ad = asb + (uint32_t)stg * ASTG, bd = bsb + (uint32_t)stg * BSTG;
        cpa16(ad + adst, Ac + (size_t)lr * lda + lc);
        cpa16(ad + adst + 64u * PADK * 2, Ac + (size_t)(lr + 64) * lda + lc);
        cpa16(bd + bdst, Bc + (size_t)lr * ldb + lc);
        if (BN == 128)
            cpa16(bd + bdst + 64u * PADK * 2, Bc + (size_t)(lr + 64) * ldb + lc);
        CP_COMMIT();
    };

    issue(0, 0);
    if (nchunks > 1) issue(1, 1);

    int s = 0, w = 2;
    for (int c = 0; c < nchunks; c++) {
        if (c + 1 < nchunks) { CP_WAIT1(); } else { CP_WAIT0(); }
        __syncthreads();
        if (c + 2 < nchunks) issue(c + 2, w);

        uint32_t ab = asb + (uint32_t)s * ASTG, bb = bsb + (uint32_t)s * BSTG;
#pragma unroll
        for (int ks = 0; ks < 2; ks++) {
            uint32_t af[2][4];
            ldsm4(af[0][0], af[0][1], af[0][2], af[0][3], ab + aoff[0] + ks * 32);
            ldsm4(af[1][0], af[1][1], af[1][2], af[1][3], ab + aoff[1] + ks * 32);
#pragma unroll
            for (int n2 = 0; n2 < NF / 2; n2++) {
                uint32_t bf[4];
                ldsm4(bf[0], bf[1], bf[2], bf[3], bb + boff[n2] + ks * 32);
                mma16816(acc[0][2 * n2],     af[0], bf + 0);
                mma16816(acc[0][2 * n2 + 1], af[0], bf + 2);
                mma16816(acc[1][2 * n2],     af[1], bf + 0);
                mma16816(acc[1][2 * n2 + 1], af[1], bf + 2);
            }
        }
        s = (s == 2) ? 0 : s + 1;
        w = (w == 2) ? 0 : w + 1;
    }
}

#define SMEM_GEMM (6 * 128 * PADK * 2)                      // 61440
#define SMEM_AV   (3 * 128 * APAD + 3 * 64 * APAD)          // 27648

// ---------------- fused prep: zero r, cvt X->bf16, transpose W -----------------
__global__ __launch_bounds__(256) void prep_kernel(
    const float* __restrict__ X,
    const float* __restrict__ Wq, const float* __restrict__ Wk,
    const float* __restrict__ Wv, const float* __restrict__ Wo,
    __nv_bfloat16* __restrict__ Xb, __nv_bfloat16* __restrict__ Wt,
    float* __restrict__ r)
{
    __shared__ float t[32][33];
    int b = blockIdx.x;
    if (b < 576) {                       // zero 6*NH*SEQ floats
        r[b * 256 + threadIdx.x] = 0.f;
        return;
    }
    b -= 576;
    if (b < 1536) {                      // cvt X
        int i = (b * 256 + threadIdx.x) * 4;
        float4 v = *(const float4*)(X + i);
        __nv_bfloat162 p0 = __floats2bfloat162_rn(v.x, v.y);
        __nv_bfloat162 p1 = __floats2bfloat162_rn(v.z, v.w);
        uint2 o = make_uint2(*(uint32_t*)&p0, *(uint32_t*)&p1);
        *(uint2*)(Xb + i) = o;
        return;
    }
    b -= 1536;                           // wtrans: 4 * 24 * 24 blocks
    int z = b / 576;
    int rem = b % 576;
    int n0 = (rem % 24) * 32, k0 = (rem / 24) * 32;
    const float* W = (z == 0) ? Wq : (z == 1) ? Wk : (z == 2) ? Wv : Wo;
    int tx = threadIdx.x & 31, ty = threadIdx.x >> 5;
#pragma unroll
    for (int q = 0; q < 4; q++)
        t[ty + q * 8][tx] = W[(size_t)(k0 + ty + q * 8) * EMB + n0 + tx];
    __syncthreads();
    __nv_bfloat16* O = Wt + (size_t)z * EMB * EMB;
#pragma unroll
    for (int q = 0; q < 4; q++)
        O[(size_t)(n0 + ty + q * 8) * EMB + k0 + tx] = __float2bfloat16(t[tx][ty + q * 8]);
}

// Vt8[h][d][j] = e4m3( V[j][h*64+d] * (MU / r5_raw[h][j]) * 16 )
__global__ __launch_bounds__(256) void vt_prep_kernel(
    const __nv_bfloat16* __restrict__ Vb, const float* __restrict__ braw,
    unsigned char* __restrict__ Vt)
{
    int h = blockIdx.y, j0 = blockIdx.x * 64;
    __shared__ float t[64][65];
    int tid = threadIdx.x;
    int jj = tid >> 2, d0 = (tid & 3) * 16;
    const __nv_bfloat16* src = Vb + (size_t)(j0 + jj) * EMB + h * HD + d0;
    __nv_bfloat16 tmp[16];
    *(uint4*)tmp = *(const uint4*)src;
    *(uint4*)(tmp + 8) = *(const uint4*)(src + 8);
#pragma unroll
    for (int q = 0; q < 16; q++) t[jj][d0 + q] = __bfloat162float(tmp[q]);
    __syncthreads();
    int dd = tid >> 2, jb = (tid & 3) * 16;
    uint16_t o[8];
#pragma unroll
    for (int q = 0; q < 8; q++) {
        int j = j0 + jb + 2 * q;
        float b0 = VSCALE * MU_F / braw[h * SEQ + j];
        float b1 = VSCALE * MU_F / braw[h * SEQ + j + 1];
        o[q] = pk_e4m3(t[jb + 2 * q][dd] * b0, t[jb + 2 * q + 1][dd] * b1);
    }
    unsigned char* dst = Vt + ((size_t)h * HD + dd) * SEQ + j0 + jb;
    *(uint4*)dst = *(uint4*)o;
}

// ---------------- QKV projection ----------------------------------------------
__global__ __launch_bounds__(256, 2) void proj_kernel(
    const __nv_bfloat16* __restrict__ Xb, const __nv_bfloat16* __restrict__ Wt,
    const float* __restrict__ bq, const float* __restrict__ bk,
    const float* __restrict__ bv, __nv_bfloat16* __restrict__ Out)
{
    extern __shared__ char dsm[];
    __nv_bfloat16* As = (__nv_bfloat16*)dsm;
    __nv_bfloat16* Bs = (__nv_bfloat16*)(dsm + 3 * 128 * PADK * 2);
    int z = blockIdx.z;
    int n0 = blockIdx.x * 128, i0 = blockIdx.y * 128;
    const float* bias = (z == 0) ? bq : (z == 1) ? bk : bv;
    float scale = (z == 0) ? 0.125f : 1.0f;

    float acc[2][8][4];
    gemm_core3<128>(Xb + (size_t)i0 * EMB, EMB,
                    Wt + (size_t)z * EMB * EMB + (size_t)n0 * EMB, EMB,
                    EMB / 32, As, Bs, acc);

    int lane = threadIdx.x & 31, wid = threadIdx.x >> 5;
    int wm = wid >> 1, wn = wid & 1;
    int r0 = wm * 32 + (lane >> 2), cb = wn * 64 + (lane & 3) * 2;
    __nv_bfloat16* O = Out + (size_t)z * SEQ * EMB;
#pragma unroll
    for (int mi = 0; mi < 2; mi++)
#pragma unroll
        for (int m8 = 0; m8 < 2; m8++) {
            int row = i0 + r0 + mi * 16 + m8 * 8;
#pragma unroll
            for (int ni = 0; ni < 8; ni++) {
                int col = n0 + cb + ni * 8;
                float f0 = (acc[mi][ni][m8 * 2 + 0] + bias[col])     * scale;
                float f1 = (acc[mi][ni][m8 * 2 + 1] + bias[col + 1]) * scale;
                __nv_bfloat162 p = __floats2bfloat162_rn(f0, f1);
                *(uint32_t*)(O + (size_t)row * EMB + col) = *(uint32_t*)&p;
            }
        }
}

// ---------------- E = exp(QK^T/8) (e4m3) + raw row sums -> r0 ------------------
__global__ __launch_bounds__(256, 2) void qk_kernel(
    const __nv_bfloat16* __restrict__ QKV, float* __restrict__ rsumg)
{
    extern __shared__ char dsm[];
    __nv_bfloat16* As = (__nv_bfloat16*)dsm;
    __nv_bfloat16* Bs = (__nv_bfloat16*)(dsm + 3 * 128 * PADK * 2);
    int j0 = blockIdx.x * 128, i0 = blockIdx.y * 128, h = blockIdx.z;

    float acc[2][8][4];
    gemm_core3<128>(QKV + (size_t)i0 * EMB + h * HD, EMB,
                    QKV + (size_t)SEQ * EMB + (size_t)j0 * EMB + h * HD, EMB,
                    HD / 32, As, Bs, acc);

    unsigned char* Et = (unsigned char*)dsm;
    float* rsumS = (float*)(dsm + 128 * 144);
    int tid = threadIdx.x, lane = tid & 31, wid = tid >> 5;
    int wm = wid >> 1, wn = wid & 1;
    int r0 = wm * 32 + (lane >> 2), cb = wn * 64 + (lane & 3) * 2;

    __syncthreads();
    if (tid < 128) rsumS[tid] = 0.f;

    float rs_sv[4];
    int lrow_sv[4];
    int idx = 0;
#pragma unroll
    for (int mi = 0; mi < 2; mi++)
#pragma unroll
        for (int m8 = 0; m8 < 2; m8++) {
            int lrow = r0 + mi * 16 + m8 * 8;
            float rs = 0.f;
#pragma unroll
            for (int ni = 0; ni < 8; ni++) {
                float e0 = __expf(acc[mi][ni][m8 * 2 + 0]);
                float e1 = __expf(acc[mi][ni][m8 * 2 + 1]);
                rs += e0 + e1;
                *(uint16_t*)(Et + lrow * 144 + cb + ni * 8) = pk_e4m3(e0, e1);
            }
            rs += __shfl_xor_sync(0xffffffffu, rs, 1);
            rs += __shfl_xor_sync(0xffffffffu, rs, 2);
            rs_sv[idx] = rs; lrow_sv[idx] = lrow; idx++;
        }
    __syncthreads();
#pragma unroll
    for (int q = 0; q < 4; q++)
        if ((lane & 3) == 0) atomicAdd(&rsumS[lrow_sv[q]], rs_sv[q]);
    __syncthreads();

    int row = tid >> 1, half = (tid & 1) * 64;
    const uint4* src = (const uint4*)(Et + row * 144 + half);
    uint4* dst = (uint4*)(g_E8 + ((size_t)h * SEQ + i0 + row) * SEQ + j0 + half);
    dst[0] = src[0]; dst[1] = src[1]; dst[2] = src[2]; dst[3] = src[3];
    if (tid < 128)
        atomicAdd(&rsumg[h * SEQ + i0 + tid], rsumS[tid]);
}

// ---------------- Sinkhorn streaming pass (round-9 config, dynamic smem) -------
// Layout: tiles[2][TILEB] @0, arow @2*TILEB, bs @2*TILEB+64 (fused pass only).
// DO_ROW=true : rowout[i] = s_i = sum_j E_ij*(MU/inraw[j]); colout[j] += E_ij*(MU/s_i)
// DO_ROW=false: colout[j] += E_ij*(MU/inraw[i])
template<bool DO_ROW>
__global__ __launch_bounds__(256) void sink_pass(
    const float* __restrict__ inraw, float* __restrict__ rowout,
    float* __restrict__ colout)
{
    extern __shared__ char sm[];
    char* tiles = sm;
    float* arow = (float*)(sm + 2 * TILEB);
    float* bs = (float*)(sm + 2 * TILEB + 64);
    int h = blockIdx.y, i0 = blockIdx.x * SINK_ROWS;
    int tid = threadIdx.x, lane = tid & 31, wid = tid >> 5;

    if (DO_ROW) {
        for (int j = tid; j < SEQ; j += 256) bs[j] = MU_F / inraw[h * SEQ + j];
    }

    const int lrow = tid >> 4, lcb = (tid & 15) * 16;
    const unsigned char* Eb = g_E8 + ((size_t)h * SEQ + i0) * SEQ;
    const uint32_t tbase = smem_u32(tiles);

    auto issue = [&](int t, int stg) {
        const unsigned char* src = Eb + (size_t)(t * TROWS + lrow) * SEQ + lcb;
        uint32_t dst = tbase + (uint32_t)stg * TILEB + lrow * TPAD + lcb;
#pragma unroll
        for (int it = 0; it < 8; it++) cpa16(dst + it * 256, src + it * 256);
        CP_COMMIT();
    };

    float ac[8];
#pragma unroll
    for (int q = 0; q < 8; q++) ac[q] = 0.f;

    issue(0, 0);

    for (int t = 0; t < SINK_NT; t++) {
        int s = t & 1;
        if (t + 1 < SINK_NT) { issue(t + 1, s ^ 1); CP_WAIT1(); }
        else { CP_WAIT0(); }
        __syncthreads();

        if (DO_ROW) {
#pragma unroll
            for (int rr = 0; rr < 2; rr++) {
                int row = wid * 2 + rr;
                const char* trow = tiles + s * TILEB + row * TPAD;
                float sum = 0.f;
#pragma unroll
                for (int k = 0; k < 4; k++) {
                    int colb = lane * 16 + k * 512;
                    uint4 u = *(const uint4*)(trow + colb);
                    const uint32_t wbuf[4] = {u.x, u.y, u.z, u.w};
#pragma unroll
                    for (int m = 0; m < 4; m++) {
                        float2 lo, hi;
                        dec4(wbuf[m], lo, hi);
                        const float* bp = bs + colb + m * 4;
                        sum += lo.x * bp[0] + lo.y * bp[1] + hi.x * bp[2] + hi.y * bp[3];
                    }
                }
#pragma unroll
                for (int o = 16; o; o >>= 1) sum += __shfl_xor_sync(0xffffffffu, sum, o);
                if (lane == 0) {
                    rowout[h * SEQ + i0 + t * TROWS + row] = sum;
                    arow[row] = MU_F / sum;
                }
            }
        } else {
            if (tid < TROWS)
                arow[tid] = MU_F / inraw[h * SEQ + i0 + t * TROWS + tid];
        }
        __syncthreads();

        // column accumulate: thread owns cols tid*8 .. tid*8+7
#pragma unroll
        for (int r = 0; r < TROWS; r++) {
            uint2 u = *(const uint2*)(tiles + s * TILEB + r * TPAD + tid * 8);
            float a = arow[r];
            float2 lo, hi, lo2, hi2;
            dec4(u.x, lo, hi);
            dec4(u.y, lo2, hi2);
            ac[0] += lo.x * a;  ac[1] += lo.y * a;
            ac[2] += hi.x * a;  ac[3] += hi.y * a;
            ac[4] += lo2.x * a; ac[5] += lo2.y * a;
            ac[6] += hi2.x * a; ac[7] += hi2.y * a;
        }
        __syncthreads();
    }

    float* cp = colout + h * SEQ + tid * 8;
#pragma unroll
    for (int q = 0; q < 8; q++) atomicAdd(cp + q, ac[q]);
}

// ---------------- ctx = diag(1/r4) * E * (diag(b) V)  — native fp8 mma ---------
__global__ __launch_bounds__(256, 2) void av_kernel(
    const unsigned char* __restrict__ Vt, const float* __restrict__ araw,
    __nv_bfloat16* __restrict__ ctx)
{
    extern __shared__ char dsm[];
    char* As = dsm;                      // 3 stages 128 x APAD
    char* Bs = dsm + 3 * 128 * APAD;     // 3 stages 64 x APAD
    int i0 = blockIdx.x * 128, h = blockIdx.y;
    const int tid = threadIdx.x, lane = tid & 31, wid = tid >> 5;
    const int wm = wid >> 1, wn = wid & 1;
    const uint32_t asb = smem_u32(As), bsb = smem_u32(Bs);
    const uint32_t ASTG = 128 * APAD, BSTG = 64 * APAD;
    const int NCH = SEQ / 32;

    const int arow = tid >> 1, acol = (tid & 1) * 16;
    const unsigned char* Ag = g_E8 + ((size_t)h * SEQ + i0 + arow) * SEQ + acol;
    const uint32_t adst = (uint32_t)(arow * APAD + acol);
    const int brow = tid >> 1, bcol = (tid & 1) * 16;
    const unsigned char* Bg = Vt + ((size_t)h * HD + brow) * SEQ + bcol;
    const uint32_t bdst = (uint32_t)(brow * APAD + bcol);
    const bool bload = (tid < 128);

    uint32_t aoff[2], boff[2];
#pragma unroll
    for (int mi = 0; mi < 2; mi++) {
        int r = wm * 32 + mi * 16 + (lane & 15);
        aoff[mi] = (uint32_t)(r * APAD + (lane >> 4) * 16);
    }
#pragma unroll
    for (int n2 = 0; n2 < 2; n2++) {
        int g = lane >> 3;
        int r = wn * 32 + n2 * 16 + ((g >> 1) << 3) + (lane & 7);
        boff[n2] = (uint32_t)(r * APAD + (g & 1) * 16);
    }

    float acc[2][4][4];
#pragma unroll
    for (int mi = 0; mi < 2; mi++)
#pragma unroll
        for (int ni = 0; ni < 4; ni++)
#pragma unroll
            for (int q = 0; q < 4; q++) acc[mi][ni][q] = 0.f;

    auto issue = [&](int c, int stg) {
        cpa16(asb + (uint32_t)stg * ASTG + adst, Ag + c * 32);
        if (bload) cpa16(bsb + (uint32_t)stg * BSTG + bdst, Bg + c * 32);
        CP_COMMIT();
    };

    issue(0, 0);
    issue(1, 1);

    int s = 0, w = 2;
    for (int c = 0; c < NCH; c++) {
        if (c + 1 < NCH) { CP_WAIT1(); } else { CP_WAIT0(); }
        __syncthreads();
        if (c + 2 < NCH) issue(c + 2, w);

        uint32_t ab = asb + (uint32_t)s * ASTG, bb = bsb + (uint32_t)s * BSTG;
        uint32_t af[2][4];
        ldsm4(af[0][0], af[0][1], af[0][2], af[0][3], ab + aoff[0]);
        ldsm4(af[1][0], af[1][1], af[1][2], af[1][3], ab + aoff[1]);
#pragma unroll
        for (int n2 = 0; n2 < 2; n2++) {
            uint32_t bf[4];
            ldsm4(bf[0], bf[1], bf[2], bf[3], bb + boff[n2]);
            mma16832q(acc[0][2 * n2],     af[0], bf + 0);
            mma16832q(acc[0][2 * n2 + 1], af[0], bf + 2);
            mma16832q(acc[1][2 * n2],     af[1], bf + 0);
            mma16832q(acc[1][2 * n2 + 1], af[1], bf + 2);
        }
        s = (s == 2) ? 0 : s + 1;
        w = (w == 2) ? 0 : w + 1;
    }

    int r0 = wm * 32 + (lane >> 2), cb = wn * 32 + (lane & 3) * 2;
#pragma unroll
    for (int mi = 0; mi < 2; mi++)
#pragma unroll
        for (int m8 = 0; m8 < 2; m8++) {
            int row = i0 + r0 + mi * 16 + m8 * 8;
            float sc = 1.0f / (araw[h * SEQ + row] * VSCALE);
            __nv_bfloat16* O = ctx + (size_t)row * EMB + h * HD;
#pragma unroll
            for (int ni = 0; ni < 4; ni++) {
                float f0 = acc[mi][ni][m8 * 2 + 0] * sc;
                float f1 = acc[mi][ni][m8 * 2 + 1] * sc;
                __nv_bfloat162 p = __floats2bfloat162_rn(f0, f1);
                *(uint32_t*)(O + cb + ni * 8) = *(uint32_t*)&p;
            }
        }
}

// ---------------- y = ctx @ Wo + bo + X ----------------------------------------
__global__ __launch_bounds__(256, 2) void final_kernel(
    const __nv_bfloat16* __restrict__ ctx, const __nv_bfloat16* __restrict__ Wt,
    const float* __restrict__ bo, const float* __restrict__ X,
    float* __restrict__ Y)
{
    extern __shared__ char dsm[];
    __nv_bfloat16* As = (__nv_bfloat16*)dsm;
    __nv_bfloat16* Bs = (__nv_bfloat16*)(dsm + 3 * 128 * PADK * 2);
    int n0 = blockIdx.x * 128, i0 = blockIdx.y * 128;

    float acc[2][8][4];
    gemm_core3<128>(ctx + (size_t)i0 * EMB, EMB,
                    Wt + (size_t)3 * EMB * EMB + (size_t)n0 * EMB, EMB,
                    EMB / 32, As, Bs, acc);

    int lane = threadIdx.x & 31, wid = threadIdx.x >> 5;
    int wm = wid >> 1, wn = wid & 1;
    int r0 = wm * 32 + (lane >> 2), cb = wn * 64 + (lane & 3) * 2;
#pragma unroll
    for (int mi = 0; mi < 2; mi++)
#pragma unroll
        for (int m8 = 0; m8 < 2; m8++) {
            int row = i0 + r0 + mi * 16 + m8 * 8;
#pragma unroll
            for (int ni = 0; ni < 8; ni++) {
                int col = n0 + cb + ni * 8;
                float2 xv = *(const float2*)(X + (size_t)row * EMB + col);
                float2 o;
                o.x = acc[mi][ni][m8 * 2 + 0] + bo[col]     + xv.x;
                o.y = acc[mi][ni][m8 * 2 + 1] + bo[col + 1] + xv.y;
                *(float2*)(Y + (size_t)row * EMB + col) = o;
            }
        }
}

// ---------------- LayerNorm ---------------------------------------------------
__global__ __launch_bounds__(256) void ln_kernel(
    const float* __restrict__ y, const float* __restrict__ gam,
    const float* __restrict__ bet, float* __restrict__ out)
{
    int row = blockIdx.x;
    const float* yr = y + (size_t)row * EMB;
    int t = threadIdx.x;
    float v0 = yr[t], v1 = yr[t + 256], v2 = yr[t + 512];

    __shared__ float red[8];
    int lane = t & 31, w = t >> 5;

    float s = v0 + v1 + v2;
#pragma unroll
    for (int o = 16; o; o >>= 1) s += __shfl_xor_sync(0xffffffffu, s, o);
    if (lane == 0) red[w] = s;
    __syncthreads();
    float tot = red[0] + red[1] + red[2] + red[3] + red[4] + red[5] + red[6] + red[7];
    float mean = tot * (1.0f / EMB);

    float d0 = v0 - mean, d1 = v1 - mean, d2 = v2 - mean;
    float sq = d0 * d0 + d1 * d1 + d2 * d2;
    __syncthreads();
#pragma unroll
    for (int o = 16; o; o >>= 1) sq += __shfl_xor_sync(0xffffffffu, sq, o);
    if (lane == 0) red[w] = sq;
    __syncthreads();
    float var = (red[0]+red[1]+red[2]+red[3]+red[4]+red[5]+red[6]+red[7]) * (1.0f / EMB);
    float inv = rsqrtf(var + 1e-12f);

    float* outr = out + (size_t)row * EMB;
    outr[t]       = gam[t]       * d0 * inv + bet[t];
    outr[t + 256] = gam[t + 256] * d1 * inv + bet[t + 256];
    outr[t + 512] = gam[t + 512] * d2 * inv + bet[t + 512];
}

// ---------------- launch ------------------------------------------------------
extern "C" void kernel_launch(void* const* d_in, const int* in_sizes, int n_in,
                              void* d_out, int out_size)
{
    const float* X  = (const float*)d_in[0];
    const float* Wq = (const float*)d_in[1];
    const float* bq = (const float*)d_in[2];
    const float* Wk = (const float*)d_in[3];
    const float* bk = (const float*)d_in[4];
    const float* Wv = (const float*)d_in[5];
    const float* bv = (const float*)d_in[6];
    const float* Wo = (const float*)d_in[7];
    const float* bo = (const float*)d_in[8];
    const float* lg = (const float*)d_in[9];
    const float* lb = (const float*)d_in[10];
    float* out = (float*)d_out;

    void *pXb, *pWt, *pQKV, *pVt, *pctx, *pr, *py;
    cudaGetSymbolAddress(&pXb, g_Xb);
    cudaGetSymbolAddress(&pWt, g_Wt);
    cudaGetSymbolAddress(&pQKV, g_QKV);
    cudaGetSymbolAddress(&pVt, g_Vt8);
    cudaGetSymbolAddress(&pctx, g_ctxb);
    cudaGetSymbolAddress(&pr, g_r);
    cudaGetSymbolAddress(&py, g_y);

    __nv_bfloat16* Xb  = (__nv_bfloat16*)pXb;
    __nv_bfloat16* Wt  = (__nv_bfloat16*)pWt;
    __nv_bfloat16* QKV = (__nv_bfloat16*)pQKV;
    unsigned char* Vt  = (unsigned char*)pVt;
    __nv_bfloat16* ctx = (__nv_bfloat16*)pctx;
    float* fr = (float*)pr;
    float* fy = (float*)py;

    float* r0 = fr + 0 * NH * SEQ;
    float* r1 = fr + 1 * NH * SEQ;
    float* r2 = fr + 2 * NH * SEQ;
    float* r3 = fr + 3 * NH * SEQ;
    float* r4 = fr + 4 * NH * SEQ;
    float* r5 = fr + 5 * NH * SEQ;

    cudaFuncSetAttribute(proj_kernel,  cudaFuncAttributeMaxDynamicSharedMemorySize, SMEM_GEMM);
    cudaFuncSetAttribute(qk_kernel,    cudaFuncAttributeMaxDynamicSharedMemorySize, SMEM_GEMM);
    cudaFuncSetAttribute(av_kernel,    cudaFuncAttributeMaxDynamicSharedMemorySize, SMEM_AV);
    cudaFuncSetAttribute(final_kernel, cudaFuncAttributeMaxDynamicSharedMemorySize, SMEM_GEMM);
    cudaFuncSetAttribute(sink_pass<true>,  cudaFuncAttributeMaxDynamicSharedMemorySize, SMEM_SINK1);
    cudaFuncSetAttribute(sink_pass<false>, cudaFuncAttributeMaxDynamicSharedMemorySize, SMEM_SINK1);
    cudaFuncSetAttribute(sink_pass<true>,  cudaFuncAttributePreferredSharedMemoryCarveout, 100);
    cudaFuncSetAttribute(sink_pass<false>, cudaFuncAttributePreferredSharedMemoryCarveout, 100);

    prep_kernel<<<576 + 1536 + 2304, 256>>>(X, Wq, Wk, Wv, Wo, Xb, Wt, fr);

    proj_kernel<<<dim3(EMB / 128, SEQ / 128, 3), 256, SMEM_GEMM>>>(Xb, Wt, bq, bk, bv, QKV);

    qk_kernel<<<dim3(SEQ / 128, SEQ / 128, NH), 256, SMEM_GEMM>>>(QKV, r0);

    // Sinkhorn: 3 iterations in 3 E passes (col, fused row+col, fused row+col)
    dim3 gsink(SEQ / SINK_ROWS, NH);     // (32, 12)
    sink_pass<false><<<gsink, 256, SMEM_SINK0>>>(r0, nullptr, r1);
    sink_pass<true><<<gsink, 256, SMEM_SINK1>>>(r1, r2, r3);
    sink_pass<true><<<gsink, 256, SMEM_SINK1>>>(r3, r4, r5);

    vt_prep_kernel<<<dim3(SEQ / 64, NH), 256>>>(QKV + (size_t)2 * SEQ * EMB, r5, Vt);

    av_kernel<<<dim3(SEQ / 128, NH), 256, SMEM_AV>>>(Vt, r4, ctx);

    final_kernel<<<dim3(EMB / 128, SEQ / 128), 256, SMEM_GEMM>>>(ctx, Wt, bo, X, fy);

    ln_kernel<<<SEQ, 256>>>(fy, lg, lb, out);
}